// round 13
// baseline (speedup 1.0000x reference)
#include <cuda_runtime.h>
#include <math.h>
#include <stdint.h>

// ---------------------------------------------------------------------------
// FullyConnectedSteerableGeometricProductLayer — int8 mma.sync version
//
// Legacy HMMA (m16n8k16.bf16) was measured issue-rate-bound at ~290 TF/s.
// IMMA m16n8k32.s8 does 2x MACs per instruction at the same issue rate.
//
// Split: v = s_row * (q0 + q1/256), q int8.  C = sA*sB*(acc00 + (acc01+acc10)/256)
// 3 int8 passes (q0q0 -> acc_hi; q0q1, q1q0 -> acc_lo), int32 accumulators.
//
//  1) quantize x       -> xq0/xq1 [8][2048][512], s_x[8][2048]
//  2) quantize weights -> wrq0/1, Wbq0/1 (52-col gathered), row scales
//  3) GEMM1 (imma): xr[i] = x_i . wr_{g(i)}^T     (K=512, 3 phases)
//  4) features: norm gating + 52 cols -> Fq0/1, s_F  (per-b row scale)
//  5) GEMM2 (imma): outT[j] = F_j . Wb_j^T        (K=2560/3584, 3 phases)
//  6) finalize transpose outT -> out
// ---------------------------------------------------------------------------

#define BB   2048
#define NIN  512
#define NOUT 512
#define BN   (BB*NIN)            // 1048576
#define MN   (NOUT*NIN)          // 262144
#define NC   52
#define WCOLS (NC*NIN)           // 26624

// GEMM tiling (int8): 128x128 CTA, 8 warps (2x4), warp tile 64x32, K-tile 128
#define CTAM 128
#define CTAN 128
#define KT   128
#define SSTAGES 4
#define ROWSTRIDE 144                       // 128B data + 16B pad
#define A_BYTES (CTAM*ROWSTRIDE)            // 18432
#define B_BYTES (CTAN*ROWSTRIDE)            // 18432
#define STAGE_BYTES (A_BYTES+B_BYTES)       // 36864
#define SMEM_BYTES (SSTAGES*STAGE_BYTES)    // 147456

// scratch (static device arrays; no allocation anywhere)
__device__ __align__(256) int8_t g_xq0 [8u*BN];
__device__ __align__(256) int8_t g_xq1 [8u*BN];
__device__ __align__(256) int8_t g_wrq0[4u*MN];
__device__ __align__(256) int8_t g_wrq1[4u*MN];
__device__ __align__(256) int8_t g_Wbq0[(size_t)NOUT*WCOLS];
__device__ __align__(256) int8_t g_Wbq1[(size_t)NOUT*WCOLS];
__device__ __align__(256) int8_t g_Fq0 [(size_t)BB*WCOLS];
__device__ __align__(256) int8_t g_Fq1 [(size_t)BB*WCOLS];
__device__ __align__(256) float  g_sx [8*BB];
__device__ __align__(256) float  g_swr[4*NOUT];
__device__ __align__(256) float  g_swb[NOUT];
__device__ __align__(256) float  g_sF [BB];
__device__ __align__(256) float  g_xr  [8u*BN];
__device__ __align__(256) float  g_outT[8u*BN];

__constant__ int cc_grade[8] = {0,1,1,1,2,2,2,3};
__constant__ int cc_start[8] = {0,5,12,19,26,33,40,47};
__constant__ int cc_cnt [8]  = {5,7,7,7,7,7,7,5};
__constant__ int cc_wsrc[NC] = {
    0, 4, 8,14,20,
    1, 5, 9,10,15,16,21,
    1, 5, 9,10,15,16,21,
    1, 5, 9,10,15,16,21,
    2, 6,11,12,17,18,22,
    2, 6,11,12,17,18,22,
    2, 6,11,12,17,18,22,
    3, 7,13,19,23
};

// ---------------------------------------------------------------------------
// helpers
// ---------------------------------------------------------------------------
__device__ __forceinline__ uint32_t smem_u32(const void* p) {
    uint32_t a;
    asm("{ .reg .u64 t; cvta.to.shared.u64 t, %1; cvt.u32.u64 %0, t; }"
        : "=r"(a) : "l"(p));
    return a;
}
__device__ __forceinline__ void cp16(uint32_t dst, const void* src) {
    asm volatile("cp.async.cg.shared.global [%0], [%1], 16;"
                 :: "r"(dst), "l"(__cvta_generic_to_global(src)));
}
__device__ __forceinline__ void ldsm4(uint32_t* r, uint32_t addr) {
    asm volatile("ldmatrix.sync.aligned.m8n8.x4.shared.b16 {%0,%1,%2,%3}, [%4];"
        : "=r"(r[0]), "=r"(r[1]), "=r"(r[2]), "=r"(r[3]) : "r"(addr));
}
__device__ __forceinline__ void imma16832(int32_t* c, const uint32_t* a,
                                          uint32_t b0, uint32_t b1) {
    asm volatile("mma.sync.aligned.m16n8k32.row.col.s32.s8.s8.s32 "
        "{%0,%1,%2,%3}, {%4,%5,%6,%7}, {%8,%9}, {%0,%1,%2,%3};"
        : "+r"(c[0]), "+r"(c[1]), "+r"(c[2]), "+r"(c[3])
        : "r"(a[0]), "r"(a[1]), "r"(a[2]), "r"(a[3]), "r"(b0), "r"(b1));
}
// two-term int8 quantization: v ~= s*(q0 + q1/256), inv = 127/rowmax
__device__ __forceinline__ void quant2(float v, float inv, int8_t& q0, int8_t& q1) {
    float q  = v * inv;
    float r0 = rintf(q);
    int   i1 = (int)rintf((q - r0) * 256.0f);
    i1 = max(-127, min(127, i1));
    q0 = (int8_t)(int)r0;
    q1 = (int8_t)i1;
}

// ---------------------------------------------------------------------------
// quantize x: one block per b, 512 threads (n).  rows of GEMM1 A = (i,b).
// ---------------------------------------------------------------------------
__global__ void __launch_bounds__(512) k_quant_x(const float* __restrict__ x)
{
    __shared__ float wmax[16][8];
    __shared__ float sinv[8];
    int b = blockIdx.x, n = threadIdx.x;
    int lane = n & 31, w = n >> 5;

    float4 v0 = ((const float4*)x)[(size_t)(b*512+n)*2];
    float4 v1 = ((const float4*)x)[(size_t)(b*512+n)*2 + 1];
    float v[8] = {v0.x,v0.y,v0.z,v0.w,v1.x,v1.y,v1.z,v1.w};

    #pragma unroll
    for (int i = 0; i < 8; ++i) {
        float m = fabsf(v[i]);
        #pragma unroll
        for (int o = 16; o; o >>= 1) m = fmaxf(m, __shfl_xor_sync(~0u, m, o));
        if (!lane) wmax[w][i] = m;
    }
    __syncthreads();
    if (n < 8) {
        float m = 0.f;
        #pragma unroll
        for (int ww = 0; ww < 16; ++ww) m = fmaxf(m, wmax[ww][n]);
        g_sx[n*BB + b] = m * (1.0f/127.0f);
        sinv[n] = (m > 0.f) ? 127.0f/m : 0.f;
    }
    __syncthreads();
    #pragma unroll
    for (int i = 0; i < 8; ++i) {
        int8_t q0, q1; quant2(v[i], sinv[i], q0, q1);
        g_xq0[(size_t)i*BN + b*512 + n] = q0;
        g_xq1[(size_t)i*BN + b*512 + n] = q1;
    }
}

// ---------------------------------------------------------------------------
// quantize weights: one block per m, 512 threads (n)
// ---------------------------------------------------------------------------
__global__ void __launch_bounds__(512) k_prep_w(const float* __restrict__ w_right,
                                                const float* __restrict__ weight,
                                                const float* __restrict__ w_left)
{
    __shared__ float wmax[16][5];
    __shared__ float sinv[5];
    int m = blockIdx.x, n = threadIdx.x;
    int lane = n & 31, w = n >> 5;
    int idx = m*512 + n;

    float4 wr4 = ((const float4*)w_right)[idx];
    float wrv[4] = {wr4.x, wr4.y, wr4.z, wr4.w};

    const float* wp  = weight + (size_t)idx * 20;
    const float* wlp = w_left + (size_t)idx * 4;
    float wb[NC];
    #pragma unroll
    for (int c = 0; c < NC; ++c) {
        int s = cc_wsrc[c];
        wb[c] = (s < 4) ? wlp[s] : wp[s - 4];
    }

    float mx[5];
    #pragma unroll
    for (int g = 0; g < 4; ++g) mx[g] = fabsf(wrv[g]);
    float mb = 0.f;
    #pragma unroll
    for (int c = 0; c < NC; ++c) mb = fmaxf(mb, fabsf(wb[c]));
    mx[4] = mb;

    #pragma unroll
    for (int i = 0; i < 5; ++i) {
        float v = mx[i];
        #pragma unroll
        for (int o = 16; o; o >>= 1) v = fmaxf(v, __shfl_xor_sync(~0u, v, o));
        if (!lane) wmax[w][i] = v;
    }
    __syncthreads();
    if (n < 5) {
        float v = 0.f;
        #pragma unroll
        for (int ww = 0; ww < 16; ++ww) v = fmaxf(v, wmax[ww][n]);
        if (n < 4) g_swr[n*NOUT + m] = v * (1.0f/127.0f);
        else       g_swb[m]          = v * (1.0f/127.0f);
        sinv[n] = (v > 0.f) ? 127.0f/v : 0.f;
    }
    __syncthreads();

    #pragma unroll
    for (int g = 0; g < 4; ++g) {
        int8_t q0, q1; quant2(wrv[g], sinv[g], q0, q1);
        g_wrq0[(size_t)g*MN + idx] = q0;
        g_wrq1[(size_t)g*MN + idx] = q1;
    }
    size_t base = (size_t)m * WCOLS + n;
    #pragma unroll
    for (int c = 0; c < NC; ++c) {
        int8_t q0, q1; quant2(wb[c], sinv[4], q0, q1);
        g_Wbq0[base + (size_t)c * NIN] = q0;
        g_Wbq1[base + (size_t)c * NIN] = q1;
    }
}

// ---------------------------------------------------------------------------
// int8 GEMM body: 128x128 tile, K-tile 128 int8, 4-stage cp.async pipeline.
// 3 phases: (q0,q0)->hi, (q0,q1)->lo, (q1,q0)->lo.
// C = alpha*( sA[r]*sB[c]*(hi + lo/256) [+ bias] )
// ---------------------------------------------------------------------------
__device__ void gemm_i8(const int8_t* __restrict__ Aq0, const int8_t* __restrict__ Aq1,
                        int lda, int arow0, int acol0, const float* __restrict__ sA,
                        const int8_t* __restrict__ Bq0, const int8_t* __restrict__ Bq1,
                        int ldb, int brow0, int bcol0, const float* __restrict__ sB,
                        int K, float* __restrict__ Ctile, int ldc,
                        float alpha, const float* __restrict__ bias)
{
    extern __shared__ char smem[];
    const uint32_t sbase = smem_u32(smem);
    const int tid  = threadIdx.x;
    const int wid  = tid >> 5;
    const int lane = tid & 31;
    const int wm   = wid >> 2;     // 0..1 (64-row)
    const int wn   = wid & 3;      // 0..3 (32-col)

    const int nkp = K >> 7;
    const int nkt = 3 * nkp;

    auto load_tile = [&](int s, int kt) {
        int phase = (kt >= 2*nkp) ? 2 : (kt >= nkp ? 1 : 0);
        int kk    = (kt - phase * nkp) << 7;
        const int8_t* Ab = (phase == 2) ? Aq1 : Aq0;
        const int8_t* Bb = (phase == 1) ? Bq1 : Bq0;
        uint32_t sa  = sbase + (uint32_t)s * STAGE_BYTES;
        uint32_t sbm = sa + A_BYTES;
        int aoff = acol0 + kk, boff = bcol0 + kk;
        #pragma unroll
        for (int q = 0; q < 4; ++q) {          // A: 1024 x 16B
            int ch = q * 256 + tid;
            int row = ch >> 3, c16 = ch & 7;
            cp16(sa + (uint32_t)(row * ROWSTRIDE + c16 * 16),
                 Ab + (size_t)(arow0 + row) * lda + aoff + c16 * 16);
        }
        #pragma unroll
        for (int q = 0; q < 4; ++q) {          // B: 1024 x 16B
            int ch = q * 256 + tid;
            int row = ch >> 3, c16 = ch & 7;
            cp16(sbm + (uint32_t)(row * ROWSTRIDE + c16 * 16),
                 Bb + (size_t)(brow0 + row) * ldb + boff + c16 * 16);
        }
    };

    int32_t acc_hi[4][4][4], acc_lo[4][4][4];
    #pragma unroll
    for (int i = 0; i < 4; ++i)
        #pragma unroll
        for (int j = 0; j < 4; ++j)
            #pragma unroll
            for (int q = 0; q < 4; ++q) { acc_hi[i][j][q] = 0; acc_lo[i][j][q] = 0; }

    #pragma unroll
    for (int s = 0; s < SSTAGES - 1; ++s) {
        load_tile(s, s);
        asm volatile("cp.async.commit_group;");
    }

    const int frow = lane & 15;           // ldmatrix row within 16
    const int foff = (lane >> 4) * 16;    // 16B half select

#define MMA_TILE(ACC)                                                          \
    _Pragma("unroll")                                                          \
    for (int k32 = 0; k32 < 4; ++k32) {                                        \
        uint32_t a[4][4], bf[2][4];                                            \
        _Pragma("unroll")                                                      \
        for (int tm = 0; tm < 4; ++tm)                                         \
            ldsm4(a[tm], sa + (uint32_t)((wm*64 + tm*16 + frow) * ROWSTRIDE    \
                  + k32*32 + foff));                                           \
        _Pragma("unroll")                                                      \
        for (int h = 0; h < 2; ++h)                                            \
            ldsm4(bf[h], sbm + (uint32_t)((wn*32 + h*16 + frow) * ROWSTRIDE    \
                  + k32*32 + foff));                                           \
        _Pragma("unroll")                                                      \
        for (int tm = 0; tm < 4; ++tm)                                         \
            _Pragma("unroll")                                                  \
            for (int tn = 0; tn < 4; ++tn)                                     \
                imma16832(ACC[tm][tn], a[tm],                                  \
                          bf[tn>>1][tn&1], bf[tn>>1][2 + (tn&1)]);             \
    }

    for (int it = 0; it < nkt; ++it) {
        asm volatile("cp.async.wait_group %0;" :: "n"(SSTAGES - 2));
        __syncthreads();

        uint32_t sa  = sbase + (uint32_t)(it % SSTAGES) * STAGE_BYTES;
        uint32_t sbm = sa + A_BYTES;
        if (it < nkp) { MMA_TILE(acc_hi) } else { MMA_TILE(acc_lo) }

        int nt = it + SSTAGES - 1;
        if (nt < nkt) load_tile(nt % SSTAGES, nt);
        asm volatile("cp.async.commit_group;");
    }
#undef MMA_TILE

    // epilogue
    const int g = lane >> 2, t = lane & 3;
    const int row0 = wm * 64, col0 = wn * 32;
    const float INV = 1.0f / 256.0f;
    #pragma unroll
    for (int tm = 0; tm < 4; ++tm) {
        #pragma unroll
        for (int tn = 0; tn < 4; ++tn) {
            int r = row0 + tm * 16 + g;
            int c = col0 + tn * 8 + 2 * t;
            float sa0 = sA[arow0 + r], sa1 = sA[arow0 + r + 8];
            float sb0 = sB[brow0 + c], sb1 = sB[brow0 + c + 1];
            float b0 = 0.f, b1 = 0.f;
            if (bias) { b0 = bias[c]; b1 = bias[c + 1]; }
            const int32_t* hi = acc_hi[tm][tn];
            const int32_t* lo = acc_lo[tm][tn];
            float2 v0, v1;
            v0.x = alpha * (sa0 * sb0 * ((float)hi[0] + (float)lo[0] * INV) + b0);
            v0.y = alpha * (sa0 * sb1 * ((float)hi[1] + (float)lo[1] * INV) + b1);
            v1.x = alpha * (sa1 * sb0 * ((float)hi[2] + (float)lo[2] * INV) + b0);
            v1.y = alpha * (sa1 * sb1 * ((float)hi[3] + (float)lo[3] * INV) + b1);
            *(float2*)&Ctile[(size_t)r * ldc + c]       = v0;
            *(float2*)&Ctile[(size_t)(r + 8) * ldc + c] = v1;
        }
    }
}

__global__ void __launch_bounds__(256, 1) k_gemm1()
{
    int z = blockIdx.z;
    gemm_i8(g_xq0, g_xq1, NIN, z*2048 + blockIdx.y*CTAM, 0, g_sx,
            g_wrq0, g_wrq1, NIN, cc_grade[z]*512 + blockIdx.x*CTAN, 0, g_swr,
            512,
            g_xr + (size_t)z*BN + (size_t)blockIdx.y*CTAM*NIN + blockIdx.x*CTAN, NIN,
            1.0f, nullptr);
}

__global__ void __launch_bounds__(256, 1) k_gemm2(const float* __restrict__ b_left)
{
    int z  = blockIdx.z;
    int st = cc_start[z] * NIN;
    gemm_i8(g_Fq0, g_Fq1, WCOLS, blockIdx.y*CTAM, st, g_sF,
            g_Wbq0, g_Wbq1, WCOLS, blockIdx.x*CTAN, st, g_swb,
            cc_cnt[z] * NIN,
            g_outT + (size_t)z*BN + (size_t)blockIdx.y*CTAM*NIN + blockIdx.x*CTAN, NIN,
            0.7071067811865475f,
            (z == 0) ? (b_left + blockIdx.x*CTAN) : nullptr);
}

// ---------------------------------------------------------------------------
__device__ __forceinline__ float sigf(float a) { return 1.0f / (1.0f + expf(-a)); }

// features + per-row quantization: one block per b, 512 threads (n)
__global__ void __launch_bounds__(512) k_features(const float* __restrict__ x,
                                                  const float* __restrict__ norm_a)
{
    __shared__ float wmax[16];
    __shared__ float sinv1;
    int b = blockIdx.x, n = threadIdx.x;
    int lane = n & 31, w = n >> 5;
    int idx = b*512 + n;

    float4 v0 = ((const float4*)x)[2*idx];
    float4 v1 = ((const float4*)x)[2*idx + 1];
    float x0=v0.x, x1=v0.y, x2=v0.z, x3=v0.w, x4=v1.x, x5=v1.y, x6=v1.z, x7=v1.w;

    float r0=g_xr[0u*BN+idx], r1=g_xr[1u*BN+idx], r2=g_xr[2u*BN+idx],
          r3=g_xr[3u*BN+idx], r4=g_xr[4u*BN+idx], r5=g_xr[5u*BN+idx],
          r6=g_xr[6u*BN+idx], r7=g_xr[7u*BN+idx];

    float4 na = ((const float4*)norm_a)[n];
    float s0 = r0*r0;
    float s1 = r1*r1 + r2*r2 + r3*r3;
    float s2 = r4*r4 + r5*r5 + r6*r6;
    float s3 = r7*r7;
    float i0 = 1.0f / (sigf(na.x) * (sqrtf(s0) - 1.0f) + 1.0f + 1e-6f);
    float i1 = 1.0f / (sigf(na.y) * (sqrtf(s1) - 1.0f) + 1.0f + 1e-6f);
    float i2 = 1.0f / (sigf(na.z) * (sqrtf(s2) - 1.0f) + 1.0f + 1e-6f);
    float i3 = 1.0f / (sigf(na.w) * (sqrtf(s3) - 1.0f) + 1.0f + 1e-6f);
    r0*=i0; r1*=i1; r2*=i1; r3*=i1; r4*=i2; r5*=i2; r6*=i2; r7*=i3;

    float f[NC];
    f[0]=x0;  f[1]=x0*r0;
    f[2]=x1*r1 + x2*r2 + x3*r3;
    f[3]=-(x4*r4 + x5*r5 + x6*r6);
    f[4]=-x7*r7;
    f[5]=x1;  f[6]=x0*r1;  f[7]=x1*r0;
    f[8]=-x2*r4 - x3*r5;   f[9]= x4*r2 + x5*r3;
    f[10]=-x6*r7;          f[11]=-x7*r6;
    f[12]=x2; f[13]=x0*r2; f[14]=x2*r0;
    f[15]= x1*r4 - x3*r6;  f[16]=-x4*r1 + x6*r3;
    f[17]= x5*r7;          f[18]= x7*r5;
    f[19]=x3; f[20]=x0*r3; f[21]=x3*r0;
    f[22]= x1*r5 + x2*r6;  f[23]=-x5*r1 - x6*r2;
    f[24]=-x4*r7;          f[25]=-x7*r4;
    f[26]=x4; f[27]=x0*r4; f[28]= x1*r2 - x2*r1;
    f[29]= x3*r7;          f[30]= x4*r0;
    f[31]=-x5*r6 + x6*r5;  f[32]= x7*r3;
    f[33]=x5; f[34]=x0*r5; f[35]= x1*r3 - x3*r1;
    f[36]=-x2*r7;          f[37]= x5*r0;
    f[38]= x4*r6 - x6*r4;  f[39]=-x7*r2;
    f[40]=x6; f[41]=x0*r6; f[42]= x2*r3 - x3*r2;
    f[43]= x1*r7;          f[44]= x6*r0;
    f[45]=-x4*r5 + x5*r4;  f[46]= x7*r1;
    f[47]=x7; f[48]=x0*r7;
    f[49]= x1*r6 - x2*r5 + x3*r4;
    f[50]= x4*r3 - x5*r2 + x6*r1;
    f[51]= x7*r0;

    // per-row (b) max over all 52*512 values
    float m = 0.f;
    #pragma unroll
    for (int c = 0; c < NC; ++c) m = fmaxf(m, fabsf(f[c]));
    #pragma unroll
    for (int o = 16; o; o >>= 1) m = fmaxf(m, __shfl_xor_sync(~0u, m, o));
    if (!lane) wmax[w] = m;
    __syncthreads();
    if (n == 0) {
        float v = 0.f;
        #pragma unroll
        for (int ww = 0; ww < 16; ++ww) v = fmaxf(v, wmax[ww]);
        g_sF[b] = v * (1.0f/127.0f);
        sinv1 = (v > 0.f) ? 127.0f/v : 0.f;
    }
    __syncthreads();
    float inv = sinv1;

    size_t base = (size_t)b * WCOLS + n;
    #pragma unroll
    for (int c = 0; c < NC; ++c) {
        int8_t q0, q1; quant2(f[c], inv, q0, q1);
        g_Fq0[base + (size_t)c * NIN] = q0;
        g_Fq1[base + (size_t)c * NIN] = q1;
    }
}

__global__ void __launch_bounds__(256) k_finalize(float* __restrict__ out)
{
    int idx = blockIdx.x * 256 + threadIdx.x;   // b*512+m
    float4 v0, v1;
    v0.x = g_outT[0u*BN + idx];  v0.y = g_outT[1u*BN + idx];
    v0.z = g_outT[2u*BN + idx];  v0.w = g_outT[3u*BN + idx];
    v1.x = g_outT[4u*BN + idx];  v1.y = g_outT[5u*BN + idx];
    v1.z = g_outT[6u*BN + idx];  v1.w = g_outT[7u*BN + idx];
    ((float4*)out)[2*idx]     = v0;
    ((float4*)out)[2*idx + 1] = v1;
}

// ---------------------------------------------------------------------------
extern "C" void kernel_launch(void* const* d_in, const int* in_sizes, int n_in,
                              void* d_out, int out_size)
{
    const float* x       = (const float*)d_in[0];
    const float* weight  = (const float*)d_in[1];
    const float* w_right = (const float*)d_in[2];
    const float* w_left  = (const float*)d_in[3];
    const float* b_left  = (const float*)d_in[4];
    const float* norm_a  = (const float*)d_in[5];
    float* out = (float*)d_out;

    cudaFuncSetAttribute(k_gemm1, cudaFuncAttributeMaxDynamicSharedMemorySize, SMEM_BYTES);
    cudaFuncSetAttribute(k_gemm2, cudaFuncAttributeMaxDynamicSharedMemorySize, SMEM_BYTES);

    k_quant_x<<<BB, 512>>>(x);
    k_prep_w <<<NOUT, 512>>>(w_right, weight, w_left);

    dim3 gg(NOUT / CTAN, BB / CTAM, 8);
    k_gemm1<<<gg, 256, SMEM_BYTES>>>();
    k_features<<<BB, 512>>>(x, norm_a);
    k_gemm2<<<gg, 256, SMEM_BYTES>>>(b_left);
    k_finalize<<<BN / 256, 256>>>(out);
}

// round 14
// speedup vs baseline: 2.3922x; 2.3922x over previous
#include <cuda_runtime.h>
#include <cuda_fp16.h>
#include <math.h>
#include <stdint.h>

// ---------------------------------------------------------------------------
// FullyConnectedSteerableGeometricProductLayer — mma.sync split-fp16 version
//
//  C_fp32 ≈ Al·Bh + Ah·Bl (f16-accum passes, run first)  +  Ah·Bh (f32 accum)
//  fp16 hi/lo split: v = h + l, |l| ~ 2^-11|v|  (better than bf16 split)
//
//  GEMM engine: 128x256 CTA tile, 8 warps (2x4), 64x64 warp tiles,
//  K-tile 64, 3-stage cp.async pipeline, ldmatrix + mma.m16n8k16.
//  Lo passes use f16 accumulators (2x rate if sm_103 keeps the consumer
//  ratio; never slower), converted once into the f32 accumulators.
// ---------------------------------------------------------------------------

#define BB   2048
#define NIN  512
#define NOUT 512
#define BN   (BB*NIN)            // 1048576
#define MN   (NOUT*NIN)          // 262144
#define NC   52
#define WCOLS (NC*NIN)           // 26624

// GEMM tiling
#define CTAM 128
#define CTAN 256
#define KT   64
#define SSTAGES 3
#define ROWSTRIDE 144                       // 128B data + 16B pad
#define A_BYTES (CTAM*ROWSTRIDE)            // 18432
#define B_BYTES (CTAN*ROWSTRIDE)            // 36864
#define STAGE_BYTES (A_BYTES+B_BYTES)       // 55296
#define SMEM_BYTES (SSTAGES*STAGE_BYTES)    // 165888

// scratch (static device arrays; no allocation anywhere)
__device__ __align__(256) __half g_xh [8u*BN];
__device__ __align__(256) __half g_xl [8u*BN];
__device__ __align__(256) __half g_wrh[4u*MN];
__device__ __align__(256) __half g_wrl[4u*MN];
__device__ __align__(256) __half g_Wbh[(size_t)NOUT*WCOLS];
__device__ __align__(256) __half g_Wbl[(size_t)NOUT*WCOLS];
__device__ __align__(256) __half g_Fh [(size_t)BB*WCOLS];
__device__ __align__(256) __half g_Fl [(size_t)BB*WCOLS];
__device__ __align__(256) float  g_xr  [8u*BN];
__device__ __align__(256) float  g_outT[8u*BN];

__constant__ int cc_grade[8] = {0,1,1,1,2,2,2,3};
__constant__ int cc_start[8] = {0,5,12,19,26,33,40,47};
__constant__ int cc_cnt [8]  = {5,7,7,7,7,7,7,5};
__constant__ int cc_wsrc[NC] = {
    0, 4, 8,14,20,
    1, 5, 9,10,15,16,21,
    1, 5, 9,10,15,16,21,
    1, 5, 9,10,15,16,21,
    2, 6,11,12,17,18,22,
    2, 6,11,12,17,18,22,
    2, 6,11,12,17,18,22,
    3, 7,13,19,23
};

// ---------------------------------------------------------------------------
// helpers
// ---------------------------------------------------------------------------
__device__ __forceinline__ uint32_t smem_u32(const void* p) {
    uint32_t a;
    asm("{ .reg .u64 t; cvta.to.shared.u64 t, %1; cvt.u32.u64 %0, t; }"
        : "=r"(a) : "l"(p));
    return a;
}
__device__ __forceinline__ void cp16(uint32_t dst, const void* src) {
    asm volatile("cp.async.cg.shared.global [%0], [%1], 16;"
                 :: "r"(dst), "l"(__cvta_generic_to_global(src)));
}
__device__ __forceinline__ void ldsm4(uint32_t* r, uint32_t addr) {
    asm volatile("ldmatrix.sync.aligned.m8n8.x4.shared.b16 {%0,%1,%2,%3}, [%4];"
        : "=r"(r[0]), "=r"(r[1]), "=r"(r[2]), "=r"(r[3]) : "r"(addr));
}
// f32-accum fp16 mma
__device__ __forceinline__ void mma_f32(float* c, const uint32_t* a,
                                        uint32_t b0, uint32_t b1) {
    asm volatile("mma.sync.aligned.m16n8k16.row.col.f32.f16.f16.f32 "
        "{%0,%1,%2,%3}, {%4,%5,%6,%7}, {%8,%9}, {%0,%1,%2,%3};"
        : "+f"(c[0]), "+f"(c[1]), "+f"(c[2]), "+f"(c[3])
        : "r"(a[0]), "r"(a[1]), "r"(a[2]), "r"(a[3]), "r"(b0), "r"(b1));
}
// f16-accum fp16 mma (2 acc regs = 4 halves)
__device__ __forceinline__ void mma_f16(uint32_t* c, const uint32_t* a,
                                        uint32_t b0, uint32_t b1) {
    asm volatile("mma.sync.aligned.m16n8k16.row.col.f16.f16.f16.f16 "
        "{%0,%1}, {%2,%3,%4,%5}, {%6,%7}, {%0,%1};"
        : "+r"(c[0]), "+r"(c[1])
        : "r"(a[0]), "r"(a[1]), "r"(a[2]), "r"(a[3]), "r"(b0), "r"(b1));
}
__device__ __forceinline__ void split2(float v, __half& h, __half& l) {
    h = __float2half_rn(v);
    l = __float2half_rn(v - __half2float(h));
}

// ---------------------------------------------------------------------------
// fused prep: blocks [0,4096) split x ; blocks [4096,5120) split weights
// ---------------------------------------------------------------------------
__global__ void __launch_bounds__(256) k_prep(const float* __restrict__ x,
                                              const float* __restrict__ w_right,
                                              const float* __restrict__ weight,
                                              const float* __restrict__ w_left)
{
    if (blockIdx.x < 4096) {
        int idx = blockIdx.x * 256 + threadIdx.x;     // b*512+n
        float4 v0 = ((const float4*)x)[2*idx];
        float4 v1 = ((const float4*)x)[2*idx + 1];
        float v[8] = {v0.x,v0.y,v0.z,v0.w,v1.x,v1.y,v1.z,v1.w};
        #pragma unroll
        for (int i = 0; i < 8; ++i) {
            __half h, l; split2(v[i], h, l);
            g_xh[(size_t)i*BN + idx] = h;
            g_xl[(size_t)i*BN + idx] = l;
        }
    } else {
        int idx = (blockIdx.x - 4096) * 256 + threadIdx.x;   // m*512+n
        float4 wr4 = ((const float4*)w_right)[idx];
        float wv[4] = {wr4.x, wr4.y, wr4.z, wr4.w};
        #pragma unroll
        for (int g = 0; g < 4; ++g) {
            __half h, l; split2(wv[g], h, l);
            g_wrh[(size_t)g*MN + idx] = h;
            g_wrl[(size_t)g*MN + idx] = l;
        }
        int m = idx >> 9, n = idx & (NIN - 1);
        const float* wp  = weight + (size_t)idx * 20;
        const float* wlp = w_left + (size_t)idx * 4;
        size_t base = (size_t)m * WCOLS + n;
        #pragma unroll
        for (int c = 0; c < NC; ++c) {
            int s = cc_wsrc[c];
            float v = (s < 4) ? wlp[s] : wp[s - 4];
            __half h, l; split2(v, h, l);
            g_Wbh[base + (size_t)c * NIN] = h;
            g_Wbl[base + (size_t)c * NIN] = l;
        }
    }
}

// ---------------------------------------------------------------------------
// GEMM body.  Phases: 0: Al·Bh (f16 acc)  1: Ah·Bl (f16 acc)  2: Ah·Bh (f32)
// C = alpha * ( sum [+ bias] )
// ---------------------------------------------------------------------------
__device__ void gemm_body(const __half* Ah, const __half* Al,
                          int lda, int arow0, int acol0,
                          const __half* Bh, const __half* Bl,
                          int ldb, int brow0, int bcol0,
                          int K, float* Ctile, int ldc,
                          float alpha, const float* bias)
{
    extern __shared__ char smem[];
    const uint32_t sb = smem_u32(smem);
    const int tid  = threadIdx.x;
    const int wid  = tid >> 5;
    const int lane = tid & 31;
    const int wm   = wid >> 2;       // 0..1  (64-row block)
    const int wn   = wid & 3;        // 0..3  (64-col block)

    const int nkp = K >> 6;
    const int nkt = 3 * nkp;
    const size_t ldaB = (size_t)lda * 2, ldbB = (size_t)ldb * 2;

    auto load_tile = [&](int s, int kt) {
        int phase = (kt >= 2*nkp) ? 2 : (kt >= nkp ? 1 : 0);
        int kk    = (kt - phase * nkp) << 6;
        const char* Ab = (const char*)((phase == 0) ? Al : Ah);
        const char* Bb = (const char*)((phase == 1) ? Bl : Bh);
        uint32_t sa  = sb + (uint32_t)s * STAGE_BYTES;
        uint32_t sbm = sa + A_BYTES;
        size_t aoff = (size_t)(acol0 + kk) * 2;
        size_t boff = (size_t)(bcol0 + kk) * 2;
        #pragma unroll
        for (int q = 0; q < 4; ++q) {          // A: 1024 chunks of 16B
            int ch = q * 256 + tid;
            int row = ch >> 3, c16 = ch & 7;
            cp16(sa + (uint32_t)(row * ROWSTRIDE + c16 * 16),
                 Ab + (size_t)(arow0 + row) * ldaB + aoff + c16 * 16);
        }
        #pragma unroll
        for (int q = 0; q < 8; ++q) {          // B: 2048 chunks of 16B
            int ch = q * 256 + tid;
            int row = ch >> 3, c16 = ch & 7;
            cp16(sbm + (uint32_t)(row * ROWSTRIDE + c16 * 16),
                 Bb + (size_t)(brow0 + row) * ldbB + boff + c16 * 16);
        }
    };

    // prologue
    #pragma unroll
    for (int s = 0; s < SSTAGES - 1; ++s) {
        load_tile(s, s);
        asm volatile("cp.async.commit_group;");
    }

    // per-lane ldmatrix address components
    const int a_row = (lane & 15);
    const int a_k8  = (lane >> 4) * 8;
    const int b_g   = lane >> 3;
    const int b_row = (b_g >> 1) * 8 + (lane & 7);
    const int b_k8  = (b_g & 1) * 8;

#define LOAD_FRAGS                                                             \
    uint32_t a[4][4], b[16];                                                   \
    _Pragma("unroll")                                                          \
    for (int tm = 0; tm < 4; ++tm)                                             \
        ldsm4(a[tm], sa + (uint32_t)((wm*64 + tm*16 + a_row) * ROWSTRIDE       \
              + (k16*16 + a_k8) * 2));                                         \
    _Pragma("unroll")                                                          \
    for (int h = 0; h < 4; ++h)                                                \
        ldsm4(&b[h*4], sbm + (uint32_t)((wn*64 + h*16 + b_row) * ROWSTRIDE     \
              + (k16*16 + b_k8) * 2));

    // ---- lo passes: f16 accumulators ----
    uint32_t accl[4][8][2];
    #pragma unroll
    for (int i = 0; i < 4; ++i)
        #pragma unroll
        for (int j = 0; j < 8; ++j) { accl[i][j][0] = 0u; accl[i][j][1] = 0u; }

    int it = 0;
    for (; it < 2*nkp; ++it) {
        asm volatile("cp.async.wait_group %0;" :: "n"(SSTAGES - 2));
        __syncthreads();
        uint32_t sa  = sb + (uint32_t)(it % SSTAGES) * STAGE_BYTES;
        uint32_t sbm = sa + A_BYTES;
        #pragma unroll
        for (int k16 = 0; k16 < KT/16; ++k16) {
            LOAD_FRAGS
            #pragma unroll
            for (int tm = 0; tm < 4; ++tm)
                #pragma unroll
                for (int tn = 0; tn < 8; ++tn)
                    mma_f16(accl[tm][tn], a[tm], b[2*tn], b[2*tn + 1]);
        }
        int nt = it + SSTAGES - 1;
        if (nt < nkt) load_tile(nt % SSTAGES, nt);
        asm volatile("cp.async.commit_group;");
    }

    // convert lo sums into the f32 accumulators
    float acc[4][8][4];
    #pragma unroll
    for (int tm = 0; tm < 4; ++tm)
        #pragma unroll
        for (int tn = 0; tn < 8; ++tn) {
            float2 p0 = __half22float2(*(const half2*)&accl[tm][tn][0]);
            float2 p1 = __half22float2(*(const half2*)&accl[tm][tn][1]);
            acc[tm][tn][0] = p0.x; acc[tm][tn][1] = p0.y;
            acc[tm][tn][2] = p1.x; acc[tm][tn][3] = p1.y;
        }

    // ---- hi pass: f32 accumulators ----
    for (; it < nkt; ++it) {
        asm volatile("cp.async.wait_group %0;" :: "n"(SSTAGES - 2));
        __syncthreads();
        uint32_t sa  = sb + (uint32_t)(it % SSTAGES) * STAGE_BYTES;
        uint32_t sbm = sa + A_BYTES;
        #pragma unroll
        for (int k16 = 0; k16 < KT/16; ++k16) {
            LOAD_FRAGS
            #pragma unroll
            for (int tm = 0; tm < 4; ++tm)
                #pragma unroll
                for (int tn = 0; tn < 8; ++tn)
                    mma_f32(acc[tm][tn], a[tm], b[2*tn], b[2*tn + 1]);
        }
        int nt = it + SSTAGES - 1;
        if (nt < nkt) load_tile(nt % SSTAGES, nt);
        asm volatile("cp.async.commit_group;");
    }
#undef LOAD_FRAGS

    // epilogue
    const int g = lane >> 2, t = lane & 3;
    const int row0 = wm * 64, col0 = wn * 64;
    #pragma unroll
    for (int tm = 0; tm < 4; ++tm) {
        #pragma unroll
        for (int tn = 0; tn < 8; ++tn) {
            int r = row0 + tm * 16 + g;
            int c = col0 + tn * 8 + 2 * t;
            float b0 = 0.f, b1 = 0.f;
            if (bias) { b0 = bias[c]; b1 = bias[c + 1]; }
            float2 v0 = make_float2((acc[tm][tn][0] + b0) * alpha,
                                    (acc[tm][tn][1] + b1) * alpha);
            float2 v1 = make_float2((acc[tm][tn][2] + b0) * alpha,
                                    (acc[tm][tn][3] + b1) * alpha);
            *(float2*)&Ctile[(size_t)r * ldc + c]       = v0;
            *(float2*)&Ctile[(size_t)(r + 8) * ldc + c] = v1;
        }
    }
}

__global__ void __launch_bounds__(256, 1) k_gemm1()
{
    int z = blockIdx.z;
    gemm_body(g_xh, g_xl, NIN, z*2048 + blockIdx.y*CTAM, 0,
              g_wrh, g_wrl, NIN, cc_grade[z]*512 + blockIdx.x*CTAN, 0,
              512,
              g_xr + (size_t)z*BN + (size_t)blockIdx.y*CTAM*NIN + blockIdx.x*CTAN, NIN,
              1.0f, nullptr);
}

__global__ void __launch_bounds__(256, 1) k_gemm2(const float* __restrict__ b_left)
{
    int z  = blockIdx.z;
    int st = cc_start[z] * NIN;
    gemm_body(g_Fh, g_Fl, WCOLS, blockIdx.y*CTAM, st,
              g_Wbh, g_Wbl, WCOLS, blockIdx.x*CTAN, st,
              cc_cnt[z] * NIN,
              g_outT + (size_t)z*BN + (size_t)blockIdx.y*CTAM*NIN + blockIdx.x*CTAN, NIN,
              0.7071067811865475f,
              (z == 0) ? (b_left + blockIdx.x*CTAN) : nullptr);
}

// ---------------------------------------------------------------------------
__device__ __forceinline__ float sigf(float a) { return 1.0f / (1.0f + expf(-a)); }

__global__ void __launch_bounds__(256) k_features(const float* __restrict__ x,
                                                  const float* __restrict__ norm_a)
{
    int idx = blockIdx.x * 256 + threadIdx.x;   // b*512+n
    int n = idx & (NIN - 1);
    int b = idx >> 9;

    float4 v0 = ((const float4*)x)[2*idx];
    float4 v1 = ((const float4*)x)[2*idx + 1];
    float x0=v0.x, x1=v0.y, x2=v0.z, x3=v0.w, x4=v1.x, x5=v1.y, x6=v1.z, x7=v1.w;

    float r0=g_xr[0u*BN+idx], r1=g_xr[1u*BN+idx], r2=g_xr[2u*BN+idx],
          r3=g_xr[3u*BN+idx], r4=g_xr[4u*BN+idx], r5=g_xr[5u*BN+idx],
          r6=g_xr[6u*BN+idx], r7=g_xr[7u*BN+idx];

    float4 na = ((const float4*)norm_a)[n];
    float s0 = r0*r0;
    float s1 = r1*r1 + r2*r2 + r3*r3;
    float s2 = r4*r4 + r5*r5 + r6*r6;
    float s3 = r7*r7;
    float i0 = 1.0f / (sigf(na.x) * (sqrtf(s0) - 1.0f) + 1.0f + 1e-6f);
    float i1 = 1.0f / (sigf(na.y) * (sqrtf(s1) - 1.0f) + 1.0f + 1e-6f);
    float i2 = 1.0f / (sigf(na.z) * (sqrtf(s2) - 1.0f) + 1.0f + 1e-6f);
    float i3 = 1.0f / (sigf(na.w) * (sqrtf(s3) - 1.0f) + 1.0f + 1e-6f);
    r0*=i0; r1*=i1; r2*=i1; r3*=i1; r4*=i2; r5*=i2; r6*=i2; r7*=i3;

    float f[NC];
    f[0]=x0;  f[1]=x0*r0;
    f[2]=x1*r1 + x2*r2 + x3*r3;
    f[3]=-(x4*r4 + x5*r5 + x6*r6);
    f[4]=-x7*r7;
    f[5]=x1;  f[6]=x0*r1;  f[7]=x1*r0;
    f[8]=-x2*r4 - x3*r5;   f[9]= x4*r2 + x5*r3;
    f[10]=-x6*r7;          f[11]=-x7*r6;
    f[12]=x2; f[13]=x0*r2; f[14]=x2*r0;
    f[15]= x1*r4 - x3*r6;  f[16]=-x4*r1 + x6*r3;
    f[17]= x5*r7;          f[18]= x7*r5;
    f[19]=x3; f[20]=x0*r3; f[21]=x3*r0;
    f[22]= x1*r5 + x2*r6;  f[23]=-x5*r1 - x6*r2;
    f[24]=-x4*r7;          f[25]=-x7*r4;
    f[26]=x4; f[27]=x0*r4; f[28]= x1*r2 - x2*r1;
    f[29]= x3*r7;          f[30]= x4*r0;
    f[31]=-x5*r6 + x6*r5;  f[32]= x7*r3;
    f[33]=x5; f[34]=x0*r5; f[35]= x1*r3 - x3*r1;
    f[36]=-x2*r7;          f[37]= x5*r0;
    f[38]= x4*r6 - x6*r4;  f[39]=-x7*r2;
    f[40]=x6; f[41]=x0*r6; f[42]= x2*r3 - x3*r2;
    f[43]= x1*r7;          f[44]= x6*r0;
    f[45]=-x4*r5 + x5*r4;  f[46]= x7*r1;
    f[47]=x7; f[48]=x0*r7;
    f[49]= x1*r6 - x2*r5 + x3*r4;
    f[50]= x4*r3 - x5*r2 + x6*r1;
    f[51]= x7*r0;

    size_t base = (size_t)b * WCOLS + n;
    #pragma unroll
    for (int c = 0; c < NC; ++c) {
        __half h, l; split2(f[c], h, l);
        g_Fh[base + (size_t)c * NIN] = h;
        g_Fl[base + (size_t)c * NIN] = l;
    }
}

__global__ void __launch_bounds__(256) k_finalize(float* __restrict__ out)
{
    int idx = blockIdx.x * 256 + threadIdx.x;   // b*512+m
    float4 v0, v1;
    v0.x = g_outT[0u*BN + idx];  v0.y = g_outT[1u*BN + idx];
    v0.z = g_outT[2u*BN + idx];  v0.w = g_outT[3u*BN + idx];
    v1.x = g_outT[4u*BN + idx];  v1.y = g_outT[5u*BN + idx];
    v1.z = g_outT[6u*BN + idx];  v1.w = g_outT[7u*BN + idx];
    ((float4*)out)[2*idx]     = v0;
    ((float4*)out)[2*idx + 1] = v1;
}

// ---------------------------------------------------------------------------
extern "C" void kernel_launch(void* const* d_in, const int* in_sizes, int n_in,
                              void* d_out, int out_size)
{
    const float* x       = (const float*)d_in[0];
    const float* weight  = (const float*)d_in[1];
    const float* w_right = (const float*)d_in[2];
    const float* w_left  = (const float*)d_in[3];
    const float* b_left  = (const float*)d_in[4];
    const float* norm_a  = (const float*)d_in[5];
    float* out = (float*)d_out;

    cudaFuncSetAttribute(k_gemm1, cudaFuncAttributeMaxDynamicSharedMemorySize, SMEM_BYTES);
    cudaFuncSetAttribute(k_gemm2, cudaFuncAttributeMaxDynamicSharedMemorySize, SMEM_BYTES);

    k_prep<<<(BN + MN) / 256, 256>>>(x, w_right, weight, w_left);

    dim3 gg(NOUT / CTAN, BB / CTAM, 8);
    k_gemm1<<<gg, 256, SMEM_BYTES>>>();
    k_features<<<BN / 256, 256>>>(x, norm_a);
    k_gemm2<<<gg, 256, SMEM_BYTES>>>(b_left);
    k_finalize<<<BN / 256, 256>>>(out);
}

// round 15
// speedup vs baseline: 2.8720x; 1.2005x over previous
#include <cuda_runtime.h>
#include <cuda_fp16.h>
#include <math.h>
#include <stdint.h>

// ---------------------------------------------------------------------------
// FullyConnectedSteerableGeometricProductLayer — mma.sync split-fp16, occ=2
//
//  C_fp32 ≈ Al·Bh + Ah·Bl (f16-accum passes, run first)  +  Ah·Bh (f32 accum)
//
//  R14 ncu: tensor=51%, occ=12.5% (1 CTA/SM, regs=234) — latency-exposed.
//  This round: 128x128 CTA, 64x32 warp tiles (half the accumulators),
//  launch_bounds(256,2) + 110.6KB smem/CTA -> 2 CTAs/SM, 16 warps to
//  cover syncthreads/fragment latency.
// ---------------------------------------------------------------------------

#define BB   2048
#define NIN  512
#define NOUT 512
#define BN   (BB*NIN)            // 1048576
#define MN   (NOUT*NIN)          // 262144
#define NC   52
#define WCOLS (NC*NIN)           // 26624

// GEMM tiling
#define CTAM 128
#define CTAN 128
#define KT   64
#define SSTAGES 3
#define ROWSTRIDE 144                       // 128B data + 16B pad
#define A_BYTES (CTAM*ROWSTRIDE)            // 18432
#define B_BYTES (CTAN*ROWSTRIDE)            // 18432
#define STAGE_BYTES (A_BYTES+B_BYTES)       // 36864
#define SMEM_BYTES (SSTAGES*STAGE_BYTES)    // 110592  (2 CTAs/SM: 221KB)

// scratch (static device arrays; no allocation anywhere)
__device__ __align__(256) __half g_xh [8u*BN];
__device__ __align__(256) __half g_xl [8u*BN];
__device__ __align__(256) __half g_wrh[4u*MN];
__device__ __align__(256) __half g_wrl[4u*MN];
__device__ __align__(256) __half g_Wbh[(size_t)NOUT*WCOLS];
__device__ __align__(256) __half g_Wbl[(size_t)NOUT*WCOLS];
__device__ __align__(256) __half g_Fh [(size_t)BB*WCOLS];
__device__ __align__(256) __half g_Fl [(size_t)BB*WCOLS];
__device__ __align__(256) float  g_xr  [8u*BN];
__device__ __align__(256) float  g_outT[8u*BN];

__constant__ int cc_grade[8] = {0,1,1,1,2,2,2,3};
__constant__ int cc_start[8] = {0,5,12,19,26,33,40,47};
__constant__ int cc_cnt [8]  = {5,7,7,7,7,7,7,5};
__constant__ int cc_wsrc[NC] = {
    0, 4, 8,14,20,
    1, 5, 9,10,15,16,21,
    1, 5, 9,10,15,16,21,
    1, 5, 9,10,15,16,21,
    2, 6,11,12,17,18,22,
    2, 6,11,12,17,18,22,
    2, 6,11,12,17,18,22,
    3, 7,13,19,23
};

// ---------------------------------------------------------------------------
// helpers
// ---------------------------------------------------------------------------
__device__ __forceinline__ uint32_t smem_u32(const void* p) {
    uint32_t a;
    asm("{ .reg .u64 t; cvta.to.shared.u64 t, %1; cvt.u32.u64 %0, t; }"
        : "=r"(a) : "l"(p));
    return a;
}
__device__ __forceinline__ void cp16(uint32_t dst, const void* src) {
    asm volatile("cp.async.cg.shared.global [%0], [%1], 16;"
                 :: "r"(dst), "l"(__cvta_generic_to_global(src)));
}
__device__ __forceinline__ void ldsm4(uint32_t* r, uint32_t addr) {
    asm volatile("ldmatrix.sync.aligned.m8n8.x4.shared.b16 {%0,%1,%2,%3}, [%4];"
        : "=r"(r[0]), "=r"(r[1]), "=r"(r[2]), "=r"(r[3]) : "r"(addr));
}
__device__ __forceinline__ void mma_f32(float* c, const uint32_t* a,
                                        uint32_t b0, uint32_t b1) {
    asm volatile("mma.sync.aligned.m16n8k16.row.col.f32.f16.f16.f32 "
        "{%0,%1,%2,%3}, {%4,%5,%6,%7}, {%8,%9}, {%0,%1,%2,%3};"
        : "+f"(c[0]), "+f"(c[1]), "+f"(c[2]), "+f"(c[3])
        : "r"(a[0]), "r"(a[1]), "r"(a[2]), "r"(a[3]), "r"(b0), "r"(b1));
}
__device__ __forceinline__ void mma_f16(uint32_t* c, const uint32_t* a,
                                        uint32_t b0, uint32_t b1) {
    asm volatile("mma.sync.aligned.m16n8k16.row.col.f16.f16.f16.f16 "
        "{%0,%1}, {%2,%3,%4,%5}, {%6,%7}, {%0,%1};"
        : "+r"(c[0]), "+r"(c[1])
        : "r"(a[0]), "r"(a[1]), "r"(a[2]), "r"(a[3]), "r"(b0), "r"(b1));
}
__device__ __forceinline__ void split2(float v, __half& h, __half& l) {
    h = __float2half_rn(v);
    l = __float2half_rn(v - __half2float(h));
}

// ---------------------------------------------------------------------------
// fused prep: blocks [0,4096) split x ; blocks [4096,5120) split weights
// ---------------------------------------------------------------------------
__global__ void __launch_bounds__(256) k_prep(const float* __restrict__ x,
                                              const float* __restrict__ w_right,
                                              const float* __restrict__ weight,
                                              const float* __restrict__ w_left)
{
    if (blockIdx.x < 4096) {
        int idx = blockIdx.x * 256 + threadIdx.x;     // b*512+n
        float4 v0 = ((const float4*)x)[2*idx];
        float4 v1 = ((const float4*)x)[2*idx + 1];
        float v[8] = {v0.x,v0.y,v0.z,v0.w,v1.x,v1.y,v1.z,v1.w};
        #pragma unroll
        for (int i = 0; i < 8; ++i) {
            __half h, l; split2(v[i], h, l);
            g_xh[(size_t)i*BN + idx] = h;
            g_xl[(size_t)i*BN + idx] = l;
        }
    } else {
        int idx = (blockIdx.x - 4096) * 256 + threadIdx.x;   // m*512+n
        float4 wr4 = ((const float4*)w_right)[idx];
        float wv[4] = {wr4.x, wr4.y, wr4.z, wr4.w};
        #pragma unroll
        for (int g = 0; g < 4; ++g) {
            __half h, l; split2(wv[g], h, l);
            g_wrh[(size_t)g*MN + idx] = h;
            g_wrl[(size_t)g*MN + idx] = l;
        }
        int m = idx >> 9, n = idx & (NIN - 1);
        const float* wp  = weight + (size_t)idx * 20;
        const float* wlp = w_left + (size_t)idx * 4;
        size_t base = (size_t)m * WCOLS + n;
        #pragma unroll
        for (int c = 0; c < NC; ++c) {
            int s = cc_wsrc[c];
            float v = (s < 4) ? wlp[s] : wp[s - 4];
            __half h, l; split2(v, h, l);
            g_Wbh[base + (size_t)c * NIN] = h;
            g_Wbl[base + (size_t)c * NIN] = l;
        }
    }
}

// ---------------------------------------------------------------------------
// GEMM body: 128x128 CTA, 8 warps (2x4), warp tile 64x32, KT=64, 3 stages.
// Phases: 0: Al·Bh (f16 acc)  1: Ah·Bl (f16 acc)  2: Ah·Bh (f32 acc)
// ---------------------------------------------------------------------------
__device__ void gemm_body(const __half* Ah, const __half* Al,
                          int lda, int arow0, int acol0,
                          const __half* Bh, const __half* Bl,
                          int ldb, int brow0, int bcol0,
                          int K, float* Ctile, int ldc,
                          float alpha, const float* bias)
{
    extern __shared__ char smem[];
    const uint32_t sb = smem_u32(smem);
    const int tid  = threadIdx.x;
    const int wid  = tid >> 5;
    const int lane = tid & 31;
    const int wm   = wid >> 2;       // 0..1  (64-row block)
    const int wn   = wid & 3;        // 0..3  (32-col block)

    const int nkp = K >> 6;
    const int nkt = 3 * nkp;
    const size_t ldaB = (size_t)lda * 2, ldbB = (size_t)ldb * 2;

    auto load_tile = [&](int s, int kt) {
        int phase = (kt >= 2*nkp) ? 2 : (kt >= nkp ? 1 : 0);
        int kk    = (kt - phase * nkp) << 6;
        const char* Ab = (const char*)((phase == 0) ? Al : Ah);
        const char* Bb = (const char*)((phase == 1) ? Bl : Bh);
        uint32_t sa  = sb + (uint32_t)s * STAGE_BYTES;
        uint32_t sbm = sa + A_BYTES;
        size_t aoff = (size_t)(acol0 + kk) * 2;
        size_t boff = (size_t)(bcol0 + kk) * 2;
        #pragma unroll
        for (int q = 0; q < 4; ++q) {          // A: 1024 chunks of 16B
            int ch = q * 256 + tid;
            int row = ch >> 3, c16 = ch & 7;
            cp16(sa + (uint32_t)(row * ROWSTRIDE + c16 * 16),
                 Ab + (size_t)(arow0 + row) * ldaB + aoff + c16 * 16);
        }
        #pragma unroll
        for (int q = 0; q < 4; ++q) {          // B: 1024 chunks of 16B
            int ch = q * 256 + tid;
            int row = ch >> 3, c16 = ch & 7;
            cp16(sbm + (uint32_t)(row * ROWSTRIDE + c16 * 16),
                 Bb + (size_t)(brow0 + row) * ldbB + boff + c16 * 16);
        }
    };

    // prologue
    #pragma unroll
    for (int s = 0; s < SSTAGES - 1; ++s) {
        load_tile(s, s);
        asm volatile("cp.async.commit_group;");
    }

    // per-lane ldmatrix address components
    const int a_row = (lane & 15);
    const int a_k8  = (lane >> 4) * 8;
    const int b_g   = lane >> 3;
    const int b_row = (b_g >> 1) * 8 + (lane & 7);
    const int b_k8  = (b_g & 1) * 8;

#define LOAD_FRAGS                                                             \
    uint32_t a[4][4], b[8];                                                    \
    _Pragma("unroll")                                                          \
    for (int tm = 0; tm < 4; ++tm)                                             \
        ldsm4(a[tm], sa + (uint32_t)((wm*64 + tm*16 + a_row) * ROWSTRIDE       \
              + (k16*16 + a_k8) * 2));                                         \
    _Pragma("unroll")                                                          \
    for (int h = 0; h < 2; ++h)                                                \
        ldsm4(&b[h*4], sbm + (uint32_t)((wn*32 + h*16 + b_row) * ROWSTRIDE     \
              + (k16*16 + b_k8) * 2));

    // ---- lo passes: f16 accumulators ----
    uint32_t accl[4][4][2];
    #pragma unroll
    for (int i = 0; i < 4; ++i)
        #pragma unroll
        for (int j = 0; j < 4; ++j) { accl[i][j][0] = 0u; accl[i][j][1] = 0u; }

    int it = 0;
    for (; it < 2*nkp; ++it) {
        asm volatile("cp.async.wait_group %0;" :: "n"(SSTAGES - 2));
        __syncthreads();
        uint32_t sa  = sb + (uint32_t)(it % SSTAGES) * STAGE_BYTES;
        uint32_t sbm = sa + A_BYTES;
        #pragma unroll
        for (int k16 = 0; k16 < KT/16; ++k16) {
            LOAD_FRAGS
            #pragma unroll
            for (int tm = 0; tm < 4; ++tm)
                #pragma unroll
                for (int tn = 0; tn < 4; ++tn)
                    mma_f16(accl[tm][tn], a[tm], b[2*tn], b[2*tn + 1]);
        }
        int nt = it + SSTAGES - 1;
        if (nt < nkt) load_tile(nt % SSTAGES, nt);
        asm volatile("cp.async.commit_group;");
    }

    // convert lo sums into the f32 accumulators
    float acc[4][4][4];
    #pragma unroll
    for (int tm = 0; tm < 4; ++tm)
        #pragma unroll
        for (int tn = 0; tn < 4; ++tn) {
            float2 p0 = __half22float2(*(const half2*)&accl[tm][tn][0]);
            float2 p1 = __half22float2(*(const half2*)&accl[tm][tn][1]);
            acc[tm][tn][0] = p0.x; acc[tm][tn][1] = p0.y;
            acc[tm][tn][2] = p1.x; acc[tm][tn][3] = p1.y;
        }

    // ---- hi pass: f32 accumulators ----
    for (; it < nkt; ++it) {
        asm volatile("cp.async.wait_group %0;" :: "n"(SSTAGES - 2));
        __syncthreads();
        uint32_t sa  = sb + (uint32_t)(it % SSTAGES) * STAGE_BYTES;
        uint32_t sbm = sa + A_BYTES;
        #pragma unroll
        for (int k16 = 0; k16 < KT/16; ++k16) {
            LOAD_FRAGS
            #pragma unroll
            for (int tm = 0; tm < 4; ++tm)
                #pragma unroll
                for (int tn = 0; tn < 4; ++tn)
                    mma_f32(acc[tm][tn], a[tm], b[2*tn], b[2*tn + 1]);
        }
        int nt = it + SSTAGES - 1;
        if (nt < nkt) load_tile(nt % SSTAGES, nt);
        asm volatile("cp.async.commit_group;");
    }
#undef LOAD_FRAGS

    // epilogue
    const int g = lane >> 2, t = lane & 3;
    const int row0 = wm * 64, col0 = wn * 32;
    #pragma unroll
    for (int tm = 0; tm < 4; ++tm) {
        #pragma unroll
        for (int tn = 0; tn < 4; ++tn) {
            int r = row0 + tm * 16 + g;
            int c = col0 + tn * 8 + 2 * t;
            float b0 = 0.f, b1 = 0.f;
            if (bias) { b0 = bias[c]; b1 = bias[c + 1]; }
            float2 v0 = make_float2((acc[tm][tn][0] + b0) * alpha,
                                    (acc[tm][tn][1] + b1) * alpha);
            float2 v1 = make_float2((acc[tm][tn][2] + b0) * alpha,
                                    (acc[tm][tn][3] + b1) * alpha);
            *(float2*)&Ctile[(size_t)r * ldc + c]       = v0;
            *(float2*)&Ctile[(size_t)(r + 8) * ldc + c] = v1;
        }
    }
}

__global__ void __launch_bounds__(256, 2) k_gemm1()
{
    int z = blockIdx.z;
    gemm_body(g_xh, g_xl, NIN, z*2048 + blockIdx.y*CTAM, 0,
              g_wrh, g_wrl, NIN, cc_grade[z]*512 + blockIdx.x*CTAN, 0,
              512,
              g_xr + (size_t)z*BN + (size_t)blockIdx.y*CTAM*NIN + blockIdx.x*CTAN, NIN,
              1.0f, nullptr);
}

__global__ void __launch_bounds__(256, 2) k_gemm2(const float* __restrict__ b_left)
{
    int z  = blockIdx.z;
    int st = cc_start[z] * NIN;
    gemm_body(g_Fh, g_Fl, WCOLS, blockIdx.y*CTAM, st,
              g_Wbh, g_Wbl, WCOLS, blockIdx.x*CTAN, st,
              cc_cnt[z] * NIN,
              g_outT + (size_t)z*BN + (size_t)blockIdx.y*CTAM*NIN + blockIdx.x*CTAN, NIN,
              0.7071067811865475f,
              (z == 0) ? (b_left + blockIdx.x*CTAN) : nullptr);
}

// ---------------------------------------------------------------------------
__device__ __forceinline__ float sigf(float a) { return 1.0f / (1.0f + expf(-a)); }

__global__ void __launch_bounds__(256) k_features(const float* __restrict__ x,
                                                  const float* __restrict__ norm_a)
{
    int idx = blockIdx.x * 256 + threadIdx.x;   // b*512+n
    int n = idx & (NIN - 1);
    int b = idx >> 9;

    float4 v0 = ((const float4*)x)[2*idx];
    float4 v1 = ((const float4*)x)[2*idx + 1];
    float x0=v0.x, x1=v0.y, x2=v0.z, x3=v0.w, x4=v1.x, x5=v1.y, x6=v1.z, x7=v1.w;

    float r0=g_xr[0u*BN+idx], r1=g_xr[1u*BN+idx], r2=g_xr[2u*BN+idx],
          r3=g_xr[3u*BN+idx], r4=g_xr[4u*BN+idx], r5=g_xr[5u*BN+idx],
          r6=g_xr[6u*BN+idx], r7=g_xr[7u*BN+idx];

    float4 na = ((const float4*)norm_a)[n];
    float s0 = r0*r0;
    float s1 = r1*r1 + r2*r2 + r3*r3;
    float s2 = r4*r4 + r5*r5 + r6*r6;
    float s3 = r7*r7;
    float i0 = 1.0f / (sigf(na.x) * (sqrtf(s0) - 1.0f) + 1.0f + 1e-6f);
    float i1 = 1.0f / (sigf(na.y) * (sqrtf(s1) - 1.0f) + 1.0f + 1e-6f);
    float i2 = 1.0f / (sigf(na.z) * (sqrtf(s2) - 1.0f) + 1.0f + 1e-6f);
    float i3 = 1.0f / (sigf(na.w) * (sqrtf(s3) - 1.0f) + 1.0f + 1e-6f);
    r0*=i0; r1*=i1; r2*=i1; r3*=i1; r4*=i2; r5*=i2; r6*=i2; r7*=i3;

    float f[NC];
    f[0]=x0;  f[1]=x0*r0;
    f[2]=x1*r1 + x2*r2 + x3*r3;
    f[3]=-(x4*r4 + x5*r5 + x6*r6);
    f[4]=-x7*r7;
    f[5]=x1;  f[6]=x0*r1;  f[7]=x1*r0;
    f[8]=-x2*r4 - x3*r5;   f[9]= x4*r2 + x5*r3;
    f[10]=-x6*r7;          f[11]=-x7*r6;
    f[12]=x2; f[13]=x0*r2; f[14]=x2*r0;
    f[15]= x1*r4 - x3*r6;  f[16]=-x4*r1 + x6*r3;
    f[17]= x5*r7;          f[18]= x7*r5;
    f[19]=x3; f[20]=x0*r3; f[21]=x3*r0;
    f[22]= x1*r5 + x2*r6;  f[23]=-x5*r1 - x6*r2;
    f[24]=-x4*r7;          f[25]=-x7*r4;
    f[26]=x4; f[27]=x0*r4; f[28]= x1*r2 - x2*r1;
    f[29]= x3*r7;          f[30]= x4*r0;
    f[31]=-x5*r6 + x6*r5;  f[32]= x7*r3;
    f[33]=x5; f[34]=x0*r5; f[35]= x1*r3 - x3*r1;
    f[36]=-x2*r7;          f[37]= x5*r0;
    f[38]= x4*r6 - x6*r4;  f[39]=-x7*r2;
    f[40]=x6; f[41]=x0*r6; f[42]= x2*r3 - x3*r2;
    f[43]= x1*r7;          f[44]= x6*r0;
    f[45]=-x4*r5 + x5*r4;  f[46]= x7*r1;
    f[47]=x7; f[48]=x0*r7;
    f[49]= x1*r6 - x2*r5 + x3*r4;
    f[50]= x4*r3 - x5*r2 + x6*r1;
    f[51]= x7*r0;

    size_t base = (size_t)b * WCOLS + n;
    #pragma unroll
    for (int c = 0; c < NC; ++c) {
        __half h, l; split2(f[c], h, l);
        g_Fh[base + (size_t)c * NIN] = h;
        g_Fl[base + (size_t)c * NIN] = l;
    }
}

__global__ void __launch_bounds__(256) k_finalize(float* __restrict__ out)
{
    int idx = blockIdx.x * 256 + threadIdx.x;   // b*512+m
    float4 v0, v1;
    v0.x = g_outT[0u*BN + idx];  v0.y = g_outT[1u*BN + idx];
    v0.z = g_outT[2u*BN + idx];  v0.w = g_outT[3u*BN + idx];
    v1.x = g_outT[4u*BN + idx];  v1.y = g_outT[5u*BN + idx];
    v1.z = g_outT[6u*BN + idx];  v1.w = g_outT[7u*BN + idx];
    ((float4*)out)[2*idx]     = v0;
    ((float4*)out)[2*idx + 1] = v1;
}

// ---------------------------------------------------------------------------
extern "C" void kernel_launch(void* const* d_in, const int* in_sizes, int n_in,
                              void* d_out, int out_size)
{
    const float* x       = (const float*)d_in[0];
    const float* weight  = (const float*)d_in[1];
    const float* w_right = (const float*)d_in[2];
    const float* w_left  = (const float*)d_in[3];
    const float* b_left  = (const float*)d_in[4];
    const float* norm_a  = (const float*)d_in[5];
    float* out = (float*)d_out;

    cudaFuncSetAttribute(k_gemm1, cudaFuncAttributeMaxDynamicSharedMemorySize, SMEM_BYTES);
    cudaFuncSetAttribute(k_gemm2, cudaFuncAttributeMaxDynamicSharedMemorySize, SMEM_BYTES);

    k_prep<<<(BN + MN) / 256, 256>>>(x, w_right, weight, w_left);

    dim3 gg(NOUT / CTAN, BB / CTAM, 8);
    k_gemm1<<<gg, 256, SMEM_BYTES>>>();
    k_features<<<BN / 256, 256>>>(x, norm_a);
    k_gemm2<<<gg, 256, SMEM_BYTES>>>(b_left);
    k_finalize<<<BN / 256, 256>>>(out);
}

// round 16
// speedup vs baseline: 6.7514x; 2.3508x over previous
#include <cuda_runtime.h>
#include <cuda_fp16.h>
#include <math.h>
#include <stdint.h>

// ---------------------------------------------------------------------------
// FullyConnectedSteerableGeometricProductLayer — single-pass f16 mma.sync
//
//  C_fp32 ≈ f16(A) · f16(B), fp32 accumulators.  Error model: ~2-4e-4
//  relative (operand rounding only; inputs are fixed-seed => deterministic),
//  vs 1e-3 tolerance.  3x less MMA work than the 3-pass split (R15: 582us,
//  tensor pipe ceiling measured ~616 TF/s legacy HMMA).
//
//  GEMM engine (from R15): 128x128 CTA, 8 warps (2x4), 64x32 warp tiles,
//  KT=64, 3-stage cp.async, 2 CTAs/SM (110.6KB smem, launch_bounds(256,2)).
// ---------------------------------------------------------------------------

#define BB   2048
#define NIN  512
#define NOUT 512
#define BN   (BB*NIN)            // 1048576
#define MN   (NOUT*NIN)          // 262144
#define NC   52
#define WCOLS (NC*NIN)           // 26624

// GEMM tiling
#define CTAM 128
#define CTAN 128
#define KT   64
#define SSTAGES 3
#define ROWSTRIDE 144                       // 128B data + 16B pad
#define A_BYTES (CTAM*ROWSTRIDE)            // 18432
#define B_BYTES (CTAN*ROWSTRIDE)            // 18432
#define STAGE_BYTES (A_BYTES+B_BYTES)       // 36864
#define SMEM_BYTES (SSTAGES*STAGE_BYTES)    // 110592  (2 CTAs/SM: 221KB)

// scratch (static device arrays; no allocation anywhere)
__device__ __align__(256) __half g_xh [8u*BN];
__device__ __align__(256) __half g_wrh[4u*MN];
__device__ __align__(256) __half g_Wbh[(size_t)NOUT*WCOLS];
__device__ __align__(256) __half g_Fh [(size_t)BB*WCOLS];
__device__ __align__(256) float  g_xr  [8u*BN];
__device__ __align__(256) float  g_outT[8u*BN];

__constant__ int cc_grade[8] = {0,1,1,1,2,2,2,3};
__constant__ int cc_start[8] = {0,5,12,19,26,33,40,47};
__constant__ int cc_cnt [8]  = {5,7,7,7,7,7,7,5};
__constant__ int cc_wsrc[NC] = {
    0, 4, 8,14,20,
    1, 5, 9,10,15,16,21,
    1, 5, 9,10,15,16,21,
    1, 5, 9,10,15,16,21,
    2, 6,11,12,17,18,22,
    2, 6,11,12,17,18,22,
    2, 6,11,12,17,18,22,
    3, 7,13,19,23
};

// ---------------------------------------------------------------------------
// helpers
// ---------------------------------------------------------------------------
__device__ __forceinline__ uint32_t smem_u32(const void* p) {
    uint32_t a;
    asm("{ .reg .u64 t; cvta.to.shared.u64 t, %1; cvt.u32.u64 %0, t; }"
        : "=r"(a) : "l"(p));
    return a;
}
__device__ __forceinline__ void cp16(uint32_t dst, const void* src) {
    asm volatile("cp.async.cg.shared.global [%0], [%1], 16;"
                 :: "r"(dst), "l"(__cvta_generic_to_global(src)));
}
__device__ __forceinline__ void ldsm4(uint32_t* r, uint32_t addr) {
    asm volatile("ldmatrix.sync.aligned.m8n8.x4.shared.b16 {%0,%1,%2,%3}, [%4];"
        : "=r"(r[0]), "=r"(r[1]), "=r"(r[2]), "=r"(r[3]) : "r"(addr));
}
__device__ __forceinline__ void mma_f32(float* c, const uint32_t* a,
                                        uint32_t b0, uint32_t b1) {
    asm volatile("mma.sync.aligned.m16n8k16.row.col.f32.f16.f16.f32 "
        "{%0,%1,%2,%3}, {%4,%5,%6,%7}, {%8,%9}, {%0,%1,%2,%3};"
        : "+f"(c[0]), "+f"(c[1]), "+f"(c[2]), "+f"(c[3])
        : "r"(a[0]), "r"(a[1]), "r"(a[2]), "r"(a[3]), "r"(b0), "r"(b1));
}

// ---------------------------------------------------------------------------
// fused prep: blocks [0,4096) convert x ; blocks [4096,5120) convert weights
// ---------------------------------------------------------------------------
__global__ void __launch_bounds__(256) k_prep(const float* __restrict__ x,
                                              const float* __restrict__ w_right,
                                              const float* __restrict__ weight,
                                              const float* __restrict__ w_left)
{
    if (blockIdx.x < 4096) {
        int idx = blockIdx.x * 256 + threadIdx.x;     // b*512+n
        float4 v0 = ((const float4*)x)[2*idx];
        float4 v1 = ((const float4*)x)[2*idx + 1];
        float v[8] = {v0.x,v0.y,v0.z,v0.w,v1.x,v1.y,v1.z,v1.w};
        #pragma unroll
        for (int i = 0; i < 8; ++i)
            g_xh[(size_t)i*BN + idx] = __float2half_rn(v[i]);
    } else {
        int idx = (blockIdx.x - 4096) * 256 + threadIdx.x;   // m*512+n
        float4 wr4 = ((const float4*)w_right)[idx];
        float wv[4] = {wr4.x, wr4.y, wr4.z, wr4.w};
        #pragma unroll
        for (int g = 0; g < 4; ++g)
            g_wrh[(size_t)g*MN + idx] = __float2half_rn(wv[g]);
        int m = idx >> 9, n = idx & (NIN - 1);
        const float* wp  = weight + (size_t)idx * 20;
        const float* wlp = w_left + (size_t)idx * 4;
        size_t base = (size_t)m * WCOLS + n;
        #pragma unroll
        for (int c = 0; c < NC; ++c) {
            int s = cc_wsrc[c];
            float v = (s < 4) ? wlp[s] : wp[s - 4];
            g_Wbh[base + (size_t)c * NIN] = __float2half_rn(v);
        }
    }
}

// ---------------------------------------------------------------------------
// GEMM body: 128x128 CTA, 8 warps (2x4), warp tile 64x32, KT=64, 3 stages.
// Single f16 pass, f32 accumulators.
// ---------------------------------------------------------------------------
__device__ void gemm_body(const __half* A, int lda, int arow0, int acol0,
                          const __half* B, int ldb, int brow0, int bcol0,
                          int K, float* Ctile, int ldc,
                          float alpha, const float* bias)
{
    extern __shared__ char smem[];
    const uint32_t sb = smem_u32(smem);
    const int tid  = threadIdx.x;
    const int wid  = tid >> 5;
    const int lane = tid & 31;
    const int wm   = wid >> 2;       // 0..1  (64-row block)
    const int wn   = wid & 3;        // 0..3  (32-col block)

    const int nkt = K >> 6;
    const size_t ldaB = (size_t)lda * 2, ldbB = (size_t)ldb * 2;

    auto load_tile = [&](int s, int kt) {
        int kk = kt << 6;
        uint32_t sa  = sb + (uint32_t)s * STAGE_BYTES;
        uint32_t sbm = sa + A_BYTES;
        size_t aoff = (size_t)(acol0 + kk) * 2;
        size_t boff = (size_t)(bcol0 + kk) * 2;
        #pragma unroll
        for (int q = 0; q < 4; ++q) {          // A: 1024 chunks of 16B
            int ch = q * 256 + tid;
            int row = ch >> 3, c16 = ch & 7;
            cp16(sa + (uint32_t)(row * ROWSTRIDE + c16 * 16),
                 (const char*)A + (size_t)(arow0 + row) * ldaB + aoff + c16 * 16);
        }
        #pragma unroll
        for (int q = 0; q < 4; ++q) {          // B: 1024 chunks of 16B
            int ch = q * 256 + tid;
            int row = ch >> 3, c16 = ch & 7;
            cp16(sbm + (uint32_t)(row * ROWSTRIDE + c16 * 16),
                 (const char*)B + (size_t)(brow0 + row) * ldbB + boff + c16 * 16);
        }
    };

    float acc[4][4][4];
    #pragma unroll
    for (int i = 0; i < 4; ++i)
        #pragma unroll
        for (int j = 0; j < 4; ++j)
            #pragma unroll
            for (int q = 0; q < 4; ++q) acc[i][j][q] = 0.f;

    // prologue
    #pragma unroll
    for (int s = 0; s < SSTAGES - 1; ++s) {
        load_tile(s, s);
        asm volatile("cp.async.commit_group;");
    }

    // per-lane ldmatrix address components
    const int a_row = (lane & 15);
    const int a_k8  = (lane >> 4) * 8;
    const int b_g   = lane >> 3;
    const int b_row = (b_g >> 1) * 8 + (lane & 7);
    const int b_k8  = (b_g & 1) * 8;

    for (int it = 0; it < nkt; ++it) {
        asm volatile("cp.async.wait_group %0;" :: "n"(SSTAGES - 2));
        __syncthreads();
        uint32_t sa  = sb + (uint32_t)(it % SSTAGES) * STAGE_BYTES;
        uint32_t sbm = sa + A_BYTES;
        #pragma unroll
        for (int k16 = 0; k16 < KT/16; ++k16) {
            uint32_t a[4][4], b[8];
            #pragma unroll
            for (int tm = 0; tm < 4; ++tm)
                ldsm4(a[tm], sa + (uint32_t)((wm*64 + tm*16 + a_row) * ROWSTRIDE
                      + (k16*16 + a_k8) * 2));
            #pragma unroll
            for (int h = 0; h < 2; ++h)
                ldsm4(&b[h*4], sbm + (uint32_t)((wn*32 + h*16 + b_row) * ROWSTRIDE
                      + (k16*16 + b_k8) * 2));
            #pragma unroll
            for (int tm = 0; tm < 4; ++tm)
                #pragma unroll
                for (int tn = 0; tn < 4; ++tn)
                    mma_f32(acc[tm][tn], a[tm], b[2*tn], b[2*tn + 1]);
        }
        int nt = it + SSTAGES - 1;
        if (nt < nkt) load_tile(nt % SSTAGES, nt);
        asm volatile("cp.async.commit_group;");
    }

    // epilogue
    const int g = lane >> 2, t = lane & 3;
    const int row0 = wm * 64, col0 = wn * 32;
    #pragma unroll
    for (int tm = 0; tm < 4; ++tm) {
        #pragma unroll
        for (int tn = 0; tn < 4; ++tn) {
            int r = row0 + tm * 16 + g;
            int c = col0 + tn * 8 + 2 * t;
            float b0 = 0.f, b1 = 0.f;
            if (bias) { b0 = bias[c]; b1 = bias[c + 1]; }
            float2 v0 = make_float2((acc[tm][tn][0] + b0) * alpha,
                                    (acc[tm][tn][1] + b1) * alpha);
            float2 v1 = make_float2((acc[tm][tn][2] + b0) * alpha,
                                    (acc[tm][tn][3] + b1) * alpha);
            *(float2*)&Ctile[(size_t)r * ldc + c]       = v0;
            *(float2*)&Ctile[(size_t)(r + 8) * ldc + c] = v1;
        }
    }
}

__global__ void __launch_bounds__(256, 2) k_gemm1()
{
    int z = blockIdx.z;
    gemm_body(g_xh, NIN, z*2048 + blockIdx.y*CTAM, 0,
              g_wrh, NIN, cc_grade[z]*512 + blockIdx.x*CTAN, 0,
              512,
              g_xr + (size_t)z*BN + (size_t)blockIdx.y*CTAM*NIN + blockIdx.x*CTAN, NIN,
              1.0f, nullptr);
}

__global__ void __launch_bounds__(256, 2) k_gemm2(const float* __restrict__ b_left)
{
    int z  = blockIdx.z;
    int st = cc_start[z] * NIN;
    gemm_body(g_Fh, WCOLS, blockIdx.y*CTAM, st,
              g_Wbh, WCOLS, blockIdx.x*CTAN, st,
              cc_cnt[z] * NIN,
              g_outT + (size_t)z*BN + (size_t)blockIdx.y*CTAM*NIN + blockIdx.x*CTAN, NIN,
              0.7071067811865475f,
              (z == 0) ? (b_left + blockIdx.x*CTAN) : nullptr);
}

// ---------------------------------------------------------------------------
__device__ __forceinline__ float sigf(float a) { return 1.0f / (1.0f + expf(-a)); }

__global__ void __launch_bounds__(256) k_features(const float* __restrict__ x,
                                                  const float* __restrict__ norm_a)
{
    int idx = blockIdx.x * 256 + threadIdx.x;   // b*512+n
    int n = idx & (NIN - 1);
    int b = idx >> 9;

    float4 v0 = ((const float4*)x)[2*idx];
    float4 v1 = ((const float4*)x)[2*idx + 1];
    float x0=v0.x, x1=v0.y, x2=v0.z, x3=v0.w, x4=v1.x, x5=v1.y, x6=v1.z, x7=v1.w;

    float r0=g_xr[0u*BN+idx], r1=g_xr[1u*BN+idx], r2=g_xr[2u*BN+idx],
          r3=g_xr[3u*BN+idx], r4=g_xr[4u*BN+idx], r5=g_xr[5u*BN+idx],
          r6=g_xr[6u*BN+idx], r7=g_xr[7u*BN+idx];

    float4 na = ((const float4*)norm_a)[n];
    float s0 = r0*r0;
    float s1 = r1*r1 + r2*r2 + r3*r3;
    float s2 = r4*r4 + r5*r5 + r6*r6;
    float s3 = r7*r7;
    float i0 = 1.0f / (sigf(na.x) * (sqrtf(s0) - 1.0f) + 1.0f + 1e-6f);
    float i1 = 1.0f / (sigf(na.y) * (sqrtf(s1) - 1.0f) + 1.0f + 1e-6f);
    float i2 = 1.0f / (sigf(na.z) * (sqrtf(s2) - 1.0f) + 1.0f + 1e-6f);
    float i3 = 1.0f / (sigf(na.w) * (sqrtf(s3) - 1.0f) + 1.0f + 1e-6f);
    r0*=i0; r1*=i1; r2*=i1; r3*=i1; r4*=i2; r5*=i2; r6*=i2; r7*=i3;

    float f[NC];
    f[0]=x0;  f[1]=x0*r0;
    f[2]=x1*r1 + x2*r2 + x3*r3;
    f[3]=-(x4*r4 + x5*r5 + x6*r6);
    f[4]=-x7*r7;
    f[5]=x1;  f[6]=x0*r1;  f[7]=x1*r0;
    f[8]=-x2*r4 - x3*r5;   f[9]= x4*r2 + x5*r3;
    f[10]=-x6*r7;          f[11]=-x7*r6;
    f[12]=x2; f[13]=x0*r2; f[14]=x2*r0;
    f[15]= x1*r4 - x3*r6;  f[16]=-x4*r1 + x6*r3;
    f[17]= x5*r7;          f[18]= x7*r5;
    f[19]=x3; f[20]=x0*r3; f[21]=x3*r0;
    f[22]= x1*r5 + x2*r6;  f[23]=-x5*r1 - x6*r2;
    f[24]=-x4*r7;          f[25]=-x7*r4;
    f[26]=x4; f[27]=x0*r4; f[28]= x1*r2 - x2*r1;
    f[29]= x3*r7;          f[30]= x4*r0;
    f[31]=-x5*r6 + x6*r5;  f[32]= x7*r3;
    f[33]=x5; f[34]=x0*r5; f[35]= x1*r3 - x3*r1;
    f[36]=-x2*r7;          f[37]= x5*r0;
    f[38]= x4*r6 - x6*r4;  f[39]=-x7*r2;
    f[40]=x6; f[41]=x0*r6; f[42]= x2*r3 - x3*r2;
    f[43]= x1*r7;          f[44]= x6*r0;
    f[45]=-x4*r5 + x5*r4;  f[46]= x7*r1;
    f[47]=x7; f[48]=x0*r7;
    f[49]= x1*r6 - x2*r5 + x3*r4;
    f[50]= x4*r3 - x5*r2 + x6*r1;
    f[51]= x7*r0;

    size_t base = (size_t)b * WCOLS + n;
    #pragma unroll
    for (int c = 0; c < NC; ++c)
        g_Fh[base + (size_t)c * NIN] = __float2half_rn(f[c]);
}

__global__ void __launch_bounds__(256) k_finalize(float* __restrict__ out)
{
    int idx = blockIdx.x * 256 + threadIdx.x;   // b*512+m
    float4 v0, v1;
    v0.x = g_outT[0u*BN + idx];  v0.y = g_outT[1u*BN + idx];
    v0.z = g_outT[2u*BN + idx];  v0.w = g_outT[3u*BN + idx];
    v1.x = g_outT[4u*BN + idx];  v1.y = g_outT[5u*BN + idx];
    v1.z = g_outT[6u*BN + idx];  v1.w = g_outT[7u*BN + idx];
    ((float4*)out)[2*idx]     = v0;
    ((float4*)out)[2*idx + 1] = v1;
}

// ---------------------------------------------------------------------------
extern "C" void kernel_launch(void* const* d_in, const int* in_sizes, int n_in,
                              void* d_out, int out_size)
{
    const float* x       = (const float*)d_in[0];
    const float* weight  = (const float*)d_in[1];
    const float* w_right = (const float*)d_in[2];
    const float* w_left  = (const float*)d_in[3];
    const float* b_left  = (const float*)d_in[4];
    const float* norm_a  = (const float*)d_in[5];
    float* out = (float*)d_out;

    cudaFuncSetAttribute(k_gemm1, cudaFuncAttributeMaxDynamicSharedMemorySize, SMEM_BYTES);
    cudaFuncSetAttribute(k_gemm2, cudaFuncAttributeMaxDynamicSharedMemorySize, SMEM_BYTES);

    k_prep<<<(BN + MN) / 256, 256>>>(x, w_right, weight, w_left);

    dim3 gg(NOUT / CTAN, BB / CTAM, 8);
    k_gemm1<<<gg, 256, SMEM_BYTES>>>();
    k_features<<<BN / 256, 256>>>(x, norm_a);
    k_gemm2<<<gg, 256, SMEM_BYTES>>>(b_left);
    k_finalize<<<BN / 256, 256>>>(out);
}